// round 1
// baseline (speedup 1.0000x reference)
#include <cuda_runtime.h>

// Cubic Bezier spline evaluation.
// Inputs (metadata order):
//   d_in[0]: t              float32 [N]         (sorted, in [0,1))
//   d_in[1]: control_points float32 [S*2, 2]    (2 inner ctrl pts per segment)
//   d_in[2]: joint_points   float32 [S+1, 2]
// Output: float32 [N, 2]
//
// Per sample: u = S*t; seg = floor(u); lt = u - seg;
//   P0 = joint[seg], P1 = ctrl[2seg], P2 = ctrl[2seg+1], P3 = joint[seg+1]
//   power-basis coeffs (Bezier matrix folded in):
//     c0 = P0
//     c1 = 3(P1-P0)
//     c2 = 3P0 - 6P1 + 3P2
//     c3 = -P0 + 3P1 - 3P2 + P3
//   out = ((c3*lt + c2)*lt + c1)*lt + c0   (Horner)

struct __align__(8) F2 { float x, y; };

__device__ __forceinline__ F2 eval_one(float t, float Sf, int S,
                                       const F2* __restrict__ ctrl,
                                       const F2* __restrict__ joint) {
    float u  = t * Sf;                 // Sf = 4096 -> exact scaling
    float fs = floorf(u);
    int   seg = (int)fs;
    float lt  = u - fs;
    if (seg >= S) { seg = S - 1; lt = 1.0f; }   // parity with reference edge case
    F2 P0 = joint[seg];
    F2 P3 = joint[seg + 1];
    F2 P1 = ctrl[2 * seg];
    F2 P2 = ctrl[2 * seg + 1];

    // x axis
    float c1x = 3.0f * (P1.x - P0.x);
    float c2x = 3.0f * (P0.x - 2.0f * P1.x + P2.x);
    float c3x = fmaf(3.0f, P1.x - P2.x, P3.x - P0.x);
    float xr  = fmaf(fmaf(fmaf(c3x, lt, c2x), lt, c1x), lt, P0.x);
    // y axis
    float c1y = 3.0f * (P1.y - P0.y);
    float c2y = 3.0f * (P0.y - 2.0f * P1.y + P2.y);
    float c3y = fmaf(3.0f, P1.y - P2.y, P3.y - P0.y);
    float yr  = fmaf(fmaf(fmaf(c3y, lt, c2y), lt, c1y), lt, P0.y);

    F2 r; r.x = xr; r.y = yr;
    return r;
}

__global__ void __launch_bounds__(256)
spline_kernel(const float* __restrict__ t,
              const F2* __restrict__ ctrl,
              const F2* __restrict__ joint,
              float* __restrict__ out,
              int n, int S, float Sf)
{
    int i4 = blockIdx.x * blockDim.x + threadIdx.x;   // group of 4 samples
    int base = i4 * 4;
    if (base + 3 < n) {
        float4 tv = *reinterpret_cast<const float4*>(t + base);
        F2 r0 = eval_one(tv.x, Sf, S, ctrl, joint);
        F2 r1 = eval_one(tv.y, Sf, S, ctrl, joint);
        F2 r2 = eval_one(tv.z, Sf, S, ctrl, joint);
        F2 r3 = eval_one(tv.w, Sf, S, ctrl, joint);
        float4* o = reinterpret_cast<float4*>(out + 2 * base);
        o[0] = make_float4(r0.x, r0.y, r1.x, r1.y);
        o[1] = make_float4(r2.x, r2.y, r3.x, r3.y);
    } else {
        for (int k = base; k < n; ++k) {
            F2 r = eval_one(t[k], Sf, S, ctrl, joint);
            out[2 * k]     = r.x;
            out[2 * k + 1] = r.y;
        }
    }
}

extern "C" void kernel_launch(void* const* d_in, const int* in_sizes, int n_in,
                              void* d_out, int out_size)
{
    const float* t     = (const float*)d_in[0];
    const F2*    ctrl  = (const F2*)d_in[1];
    const F2*    joint = (const F2*)d_in[2];
    float*       out   = (float*)d_out;

    int n = in_sizes[0];
    int S = in_sizes[2] / 2 - 1;       // joint_points has (S+1)*2 floats
    float Sf = (float)S;

    int ngroups = (n + 3) / 4;
    int threads = 256;
    int blocks  = (ngroups + threads - 1) / threads;
    spline_kernel<<<blocks, threads>>>(t, ctrl, joint, out, n, S, Sf);
}

// round 4
// speedup vs baseline: 1.0014x; 1.0014x over previous
#include <cuda_runtime.h>

// Cubic Bezier spline evaluation, segment-dedup version.
//   d_in[0]: t              float32 [N]      (sorted, in [0,1))
//   d_in[1]: control_points float32 [S*2, 2]
//   d_in[2]: joint_points   float32 [S+1, 2]
// Output: float32 [N, 2]
//
// t is sorted and N/S = 2048 samples/segment, so 8 consecutive samples almost
// always share one segment. Fast path: load the 4 points once, fold the
// Bezier matrix once, do 8 Horner evals. Slow path (segment boundary inside
// the group, ~0.4% of threads): per-sample gather.

struct __align__(8) F2 { float x, y; };

// Power-basis coefficients for one segment (both axes).
struct Coeffs {
    float c0x, c1x, c2x, c3x;
    float c0y, c1y, c2y, c3y;
};

__device__ __forceinline__ Coeffs make_coeffs(int seg,
                                              const float4* __restrict__ ctrl4,
                                              const F2* __restrict__ joint) {
    F2 P0 = joint[seg];
    F2 P3 = joint[seg + 1];
    float4 cc = ctrl4[seg];          // (P1.x, P1.y, P2.x, P2.y) — 16B aligned
    float P1x = cc.x, P1y = cc.y, P2x = cc.z, P2y = cc.w;

    Coeffs c;
    c.c0x = P0.x;
    c.c1x = 3.0f * (P1x - P0.x);
    c.c2x = 3.0f * (P0.x - 2.0f * P1x + P2x);
    c.c3x = fmaf(3.0f, P1x - P2x, P3.x - P0.x);
    c.c0y = P0.y;
    c.c1y = 3.0f * (P1y - P0.y);
    c.c2y = 3.0f * (P0.y - 2.0f * P1y + P2y);
    c.c3y = fmaf(3.0f, P1y - P2y, P3.y - P0.y);
    return c;
}

__device__ __forceinline__ F2 horner(const Coeffs& c, float lt) {
    F2 r;
    r.x = fmaf(fmaf(fmaf(c.c3x, lt, c.c2x), lt, c.c1x), lt, c.c0x);
    r.y = fmaf(fmaf(fmaf(c.c3y, lt, c.c2y), lt, c.c1y), lt, c.c0y);
    return r;
}

__global__ void __launch_bounds__(256)
spline_kernel(const float* __restrict__ t,
              const float4* __restrict__ ctrl4,
              const F2* __restrict__ joint,
              float* __restrict__ out,
              int n, int S, float Sf)
{
    int gid  = blockIdx.x * blockDim.x + threadIdx.x;
    int base = gid * 8;

    if (base + 7 < n) {
        float tv[8];
        {
            float4 a = *reinterpret_cast<const float4*>(t + base);
            float4 b = *reinterpret_cast<const float4*>(t + base + 4);
            tv[0]=a.x; tv[1]=a.y; tv[2]=a.z; tv[3]=a.w;
            tv[4]=b.x; tv[5]=b.y; tv[6]=b.z; tv[7]=b.w;
        }

        int   seg[8];
        float lt[8];
        #pragma unroll
        for (int k = 0; k < 8; ++k) {
            float u  = tv[k] * Sf;
            float fs = floorf(u);
            int   s  = (int)fs;
            float l  = u - fs;
            if (s >= S) { s = S - 1; l = 1.0f; }
            seg[k] = s; lt[k] = l;
        }

        F2 r[8];
        if (seg[0] == seg[7]) {
            // Fast path: one segment for all 8 samples (~99.6% of threads).
            Coeffs c = make_coeffs(seg[0], ctrl4, joint);
            #pragma unroll
            for (int k = 0; k < 8; ++k) r[k] = horner(c, lt[k]);
        } else {
            #pragma unroll
            for (int k = 0; k < 8; ++k) {
                Coeffs c = make_coeffs(seg[k], ctrl4, joint);
                r[k] = horner(c, lt[k]);
            }
        }

        float4* o = reinterpret_cast<float4*>(out + 2 * base);
        o[0] = make_float4(r[0].x, r[0].y, r[1].x, r[1].y);
        o[1] = make_float4(r[2].x, r[2].y, r[3].x, r[3].y);
        o[2] = make_float4(r[4].x, r[4].y, r[5].x, r[5].y);
        o[3] = make_float4(r[6].x, r[6].y, r[7].x, r[7].y);
    } else {
        for (int k = base; k < n; ++k) {
            float u  = t[k] * Sf;
            float fs = floorf(u);
            int   s  = (int)fs;
            float l  = u - fs;
            if (s >= S) { s = S - 1; l = 1.0f; }
            Coeffs c = make_coeffs(s, ctrl4, joint);
            F2 rr = horner(c, l);
            out[2 * k]     = rr.x;
            out[2 * k + 1] = rr.y;
        }
    }
}

extern "C" void kernel_launch(void* const* d_in, const int* in_sizes, int n_in,
                              void* d_out, int out_size)
{
    const float*  t     = (const float*)d_in[0];
    const float4* ctrl4 = (const float4*)d_in[1];   // 2 ctrl pts/segment = 16B
    const F2*     joint = (const F2*)d_in[2];
    float*        out   = (float*)d_out;

    int n = in_sizes[0];
    int S = in_sizes[2] / 2 - 1;       // joint_points has (S+1)*2 floats
    float Sf = (float)S;

    int ngroups = (n + 7) / 8;
    int threads = 256;
    int blocks  = (ngroups + threads - 1) / threads;
    spline_kernel<<<blocks, threads>>>(t, ctrl4, joint, out, n, S, Sf);
}